// round 2
// baseline (speedup 1.0000x reference)
#include <cuda_runtime.h>
#include <cuda_bf16.h>
#include <math.h>

#define BB 32
#define TT 64
#define SS 400
#define HH 256
#define EE 128
#define VV 50000
#define H2 512

// d_out layout (fp32): vocab_dists[B,T,V], attn[B,T,S], pgen[B,T,1], h[B,H], c[B,H]
#define OFF_ATTN 102400000ull
#define OFF_PG   103219200ull
#define OFF_H    103221248ull
#define OFF_C    103229440ull

// ---------------- scratch (static device memory; no allocation) ----------------
__device__ float g_enc_feat[BB * SS * HH];    // 13.1 MB
__device__ float g_hbuf[2][BB * HH];
__device__ float g_cbuf[2][BB * HH];
__device__ float g_ctx[BB * H2];
__device__ float g_x[BB * HH];
__device__ float g_dec[BB * HH];
__device__ float g_scores[BB * SS];
__device__ float g_vred[BB * TT * HH];        // 2 MB, rows ordered r=b*T+t

__device__ __forceinline__ float sigf(float v) { return 1.0f / (1.0f + expf(-v)); }

// ---------------- init ----------------
__global__ void k_init(const float* __restrict__ h0, const float* __restrict__ c0,
                       float* __restrict__ hA, float* __restrict__ cA,
                       float* __restrict__ ctx) {
    int i = blockIdx.x * 256 + threadIdx.x;
    if (i < BB * HH) { hA[i] = h0[i]; cA[i] = c0[i]; }
    if (i < BB * H2) ctx[i] = 0.0f;
}

// ---------------- generic fp32 GEMM: C[M,N] = A[M,K] @ Bw[N,K]^T + bias ----------------
// BM=BN=128, BK=8, 256 threads, 8x8 per thread. M%128==0, K%8==0 required; N guarded.
__global__ __launch_bounds__(256) void sgemm_abt(
    const float* __restrict__ A, const float* __restrict__ Bw,
    const float* __restrict__ bias, float* __restrict__ C,
    int M, int N, int K)
{
    __shared__ float As[8][128];
    __shared__ float Bs[8][128];
    const int tid = threadIdx.x;
    const int row0 = blockIdx.y << 7;
    const int col0 = blockIdx.x << 7;
    const int tr = (tid >> 4) << 3;
    const int tc = (tid & 15) << 3;
    float acc[8][8];
#pragma unroll
    for (int i = 0; i < 8; i++)
#pragma unroll
        for (int j = 0; j < 8; j++) acc[i][j] = 0.0f;

    const int lr = tid >> 1;            // 0..127
    const int lk = (tid & 1) << 2;      // 0 or 4
    const bool bok = (col0 + lr) < N;

    for (int k0 = 0; k0 < K; k0 += 8) {
        float4 av = *(const float4*)&A[(size_t)(row0 + lr) * K + k0 + lk];
        float4 bv = bok ? *(const float4*)&Bw[(size_t)(col0 + lr) * K + k0 + lk]
                        : make_float4(0.f, 0.f, 0.f, 0.f);
        As[lk + 0][lr] = av.x; As[lk + 1][lr] = av.y; As[lk + 2][lr] = av.z; As[lk + 3][lr] = av.w;
        Bs[lk + 0][lr] = bv.x; Bs[lk + 1][lr] = bv.y; Bs[lk + 2][lr] = bv.z; Bs[lk + 3][lr] = bv.w;
        __syncthreads();
#pragma unroll
        for (int kk = 0; kk < 8; kk++) {
            float4 a0 = *(const float4*)&As[kk][tr];
            float4 a1 = *(const float4*)&As[kk][tr + 4];
            float4 b0 = *(const float4*)&Bs[kk][tc];
            float4 b1 = *(const float4*)&Bs[kk][tc + 4];
            float a[8] = {a0.x, a0.y, a0.z, a0.w, a1.x, a1.y, a1.z, a1.w};
            float b[8] = {b0.x, b0.y, b0.z, b0.w, b1.x, b1.y, b1.z, b1.w};
#pragma unroll
            for (int i = 0; i < 8; i++)
#pragma unroll
                for (int j = 0; j < 8; j++) acc[i][j] += a[i] * b[j];
        }
        __syncthreads();
    }
#pragma unroll
    for (int i = 0; i < 8; i++) {
        size_t r = row0 + tr + i;
#pragma unroll
        for (int j = 0; j < 8; j++) {
            int c = col0 + tc + j;
            if (c < N) C[r * (size_t)N + c] = acc[i][j] + (bias ? bias[c] : 0.0f);
        }
    }
}

// ---------------- x = [emb_t, ctx] @ Wr^T + br ----------------
// grid 32 blocks x 256 threads; thread = (b = tid&31, nl = tid>>5); n = blk*8+nl
__global__ __launch_bounds__(256) void k_x(
    const int* __restrict__ ids, const float* __restrict__ emb,
    const float* __restrict__ ctx, const float* __restrict__ Wr,
    const float* __restrict__ br, float* __restrict__ xout, int t)
{
    __shared__ float sA[128 * 33];
    const int tid = threadIdx.x;
    const int b = tid & 31, nl = tid >> 5;
    const int n = (blockIdx.x << 3) + nl;
    const float* wrow = Wr + (size_t)n * 640;
    float acc = 0.0f;
    for (int k0 = 0; k0 < 640; k0 += 128) {
        for (int i = tid; i < 4096; i += 256) {
            int bb = i >> 7, kk = i & 127;
            int k = k0 + kk;
            float v;
            if (k < EE) v = emb[(size_t)ids[bb * TT + t] * EE + k];
            else        v = ctx[bb * H2 + (k - EE)];
            sA[kk * 33 + bb] = v;
        }
        __syncthreads();
        const float4* w4 = (const float4*)(wrow + k0);
#pragma unroll 8
        for (int q = 0; q < 32; q++) {
            float4 w = w4[q];
            int kb = q * 4;
            acc += sA[(kb + 0) * 33 + b] * w.x + sA[(kb + 1) * 33 + b] * w.y
                 + sA[(kb + 2) * 33 + b] * w.z + sA[(kb + 3) * 33 + b] * w.w;
        }
        __syncthreads();
    }
    xout[b * HH + n] = acc + br[n];
}

// ---------------- gates + LSTM elementwise ----------------
__global__ __launch_bounds__(256) void k_gates(
    const float* __restrict__ x, const float* __restrict__ hin,
    const float* __restrict__ cin,
    const float* __restrict__ Wih, const float* __restrict__ Whh,
    const float* __restrict__ bih, const float* __restrict__ bhh,
    float* __restrict__ hout, float* __restrict__ cout)
{
    __shared__ float sA[128 * 33];
    const int tid = threadIdx.x;
    const int b = tid & 31, jl = tid >> 5;
    const int j = (blockIdx.x << 3) + jl;
    float acc0 = 0.f, acc1 = 0.f, acc2 = 0.f, acc3 = 0.f;
    for (int k0 = 0; k0 < 512; k0 += 128) {
        for (int i = tid; i < 4096; i += 256) {
            int bb = i >> 7, kk = i & 127;
            int k = k0 + kk;
            sA[kk * 33 + bb] = (k < HH) ? x[bb * HH + k] : hin[bb * HH + k - HH];
        }
        __syncthreads();
        const float* W = (k0 < 256) ? Wih : Whh;
        int koff = k0 & 255;
        const float4* w0 = (const float4*)(W + (size_t)(j) * 256 + koff);
        const float4* w1 = (const float4*)(W + (size_t)(256 + j) * 256 + koff);
        const float4* w2 = (const float4*)(W + (size_t)(512 + j) * 256 + koff);
        const float4* w3 = (const float4*)(W + (size_t)(768 + j) * 256 + koff);
#pragma unroll 4
        for (int q = 0; q < 32; q++) {
            int kb = q * 4;
            float a0 = sA[(kb + 0) * 33 + b], a1 = sA[(kb + 1) * 33 + b];
            float a2 = sA[(kb + 2) * 33 + b], a3 = sA[(kb + 3) * 33 + b];
            float4 w;
            w = w0[q]; acc0 += a0 * w.x + a1 * w.y + a2 * w.z + a3 * w.w;
            w = w1[q]; acc1 += a0 * w.x + a1 * w.y + a2 * w.z + a3 * w.w;
            w = w2[q]; acc2 += a0 * w.x + a1 * w.y + a2 * w.z + a3 * w.w;
            w = w3[q]; acc3 += a0 * w.x + a1 * w.y + a2 * w.z + a3 * w.w;
        }
        __syncthreads();
    }
    float gi = acc0 + bih[j]       + bhh[j];
    float gf = acc1 + bih[256 + j] + bhh[256 + j];
    float gg = acc2 + bih[512 + j] + bhh[512 + j];
    float go = acc3 + bih[768 + j] + bhh[768 + j];
    float co = cin[b * HH + j];
    float cn = sigf(gf) * co + sigf(gi) * tanhf(gg);
    float hn = sigf(go) * tanhf(cn);
    cout[b * HH + j] = cn;
    hout[b * HH + j] = hn;
}

// ---------------- generic 32-row linear: out = [s1|s2] @ W^T + bias ----------------
__global__ __launch_bounds__(256) void k_rowlin(
    const float* __restrict__ s1, int L1,
    const float* __restrict__ s2, int L2,
    const float* __restrict__ W, int Kw,
    const float* __restrict__ bias,
    float* __restrict__ out, int outStride)
{
    __shared__ float sA[128 * 33];
    const int tid = threadIdx.x;
    const int b = tid & 31, nl = tid >> 5;
    const int n = (blockIdx.x << 3) + nl;
    const float* wrow = W + (size_t)n * Kw;
    float acc = 0.0f;
    for (int k0 = 0; k0 < Kw; k0 += 128) {
        for (int i = tid; i < 4096; i += 256) {
            int bb = i >> 7, kk = i & 127;
            int k = k0 + kk;
            sA[kk * 33 + bb] = (k < L1) ? s1[bb * L1 + k] : s2[bb * L2 + k - L1];
        }
        __syncthreads();
        const float4* w4 = (const float4*)(wrow + k0);
#pragma unroll 4
        for (int q = 0; q < 32; q++) {
            int kb = q * 4;
            float4 w = w4[q];
            acc += sA[(kb + 0) * 33 + b] * w.x + sA[(kb + 1) * 33 + b] * w.y
                 + sA[(kb + 2) * 33 + b] * w.z + sA[(kb + 3) * 33 + b] * w.w;
        }
        __syncthreads();
    }
    out[b * outStride + n] = acc + bias[n];
}

// ---------------- attention scores ----------------
// grid (50, 32), 256 threads: warp w -> position s = blk*8+w, lanes split k.
__global__ __launch_bounds__(256) void k_scores(
    const float* __restrict__ enc_feat, const float* __restrict__ dec,
    const float* __restrict__ va, const unsigned char* __restrict__ mask,
    float* __restrict__ scores)
{
    __shared__ float sdf[256], sva[256];
    const int b = blockIdx.y;
    const int tid = threadIdx.x;
    sdf[tid] = dec[b * HH + tid];
    sva[tid] = va[tid];
    __syncthreads();
    const int w = tid >> 5, lane = tid & 31;
    const int s = blockIdx.x * 8 + w;
    const float4* ef = (const float4*)(enc_feat + ((size_t)b * SS + s) * HH);
    float acc = 0.0f;
#pragma unroll
    for (int h = 0; h < 2; h++) {
        int k4 = lane + h * 32;
        float4 e = ef[k4];
        float4 d = ((const float4*)sdf)[k4];
        float4 v = ((const float4*)sva)[k4];
        acc += v.x * tanhf(e.x + d.x) + v.y * tanhf(e.y + d.y)
             + v.z * tanhf(e.z + d.z) + v.w * tanhf(e.w + d.w);
    }
#pragma unroll
    for (int o = 16; o > 0; o >>= 1) acc += __shfl_xor_sync(0xffffffffu, acc, o);
    if (lane == 0) {
        scores[b * SS + s] = mask[b * SS + s] ? -INFINITY : acc;
    }
}

// ---------------- softmax over S + ctx + pgen (grid 32, 512 threads) ----------------
__global__ __launch_bounds__(512) void k_attn_ctx(
    const float* __restrict__ scores, const float* __restrict__ enc,
    const float* __restrict__ hn, const float* __restrict__ cn,
    const float* __restrict__ x,
    const float* __restrict__ whp, const float* __restrict__ wsp,
    const float* __restrict__ wxp, const float* __restrict__ bxp,
    float* __restrict__ ctx_out, float* __restrict__ dout, int t)
{
    __shared__ float sattn[SS];
    __shared__ float red[512];
    __shared__ float sctx[512];
    const int b = blockIdx.x, tid = threadIdx.x;

    float sc = (tid < SS) ? scores[b * SS + tid] : -INFINITY;
    red[tid] = sc;
    __syncthreads();
#pragma unroll
    for (int o = 256; o > 0; o >>= 1) {
        if (tid < o) red[tid] = fmaxf(red[tid], red[tid + o]);
        __syncthreads();
    }
    float m = red[0];
    __syncthreads();
    float e = (tid < SS) ? expf(sc - m) : 0.0f;
    red[tid] = e;
    __syncthreads();
#pragma unroll
    for (int o = 256; o > 0; o >>= 1) {
        if (tid < o) red[tid] += red[tid + o];
        __syncthreads();
    }
    float inv = 1.0f / red[0];
    __syncthreads();
    if (tid < SS) {
        float a = e * inv;
        sattn[tid] = a;
        dout[OFF_ATTN + ((size_t)b * TT + t) * SS + tid] = a;
    }
    __syncthreads();

    // ctx: 128 threads, float4 each covering 4 of 512 dims
    if (tid < 128) {
        const float4* ep = (const float4*)(enc + (size_t)b * SS * H2);
        float4 a4 = make_float4(0.f, 0.f, 0.f, 0.f);
#pragma unroll 4
        for (int s = 0; s < SS; s++) {
            float w = sattn[s];
            float4 v = ep[(size_t)s * 128 + tid];
            a4.x += w * v.x; a4.y += w * v.y; a4.z += w * v.z; a4.w += w * v.w;
        }
        ((float4*)(ctx_out + b * H2))[tid] = a4;
        int k4 = tid * 4;
        sctx[k4 + 0] = a4.x; sctx[k4 + 1] = a4.y; sctx[k4 + 2] = a4.z; sctx[k4 + 3] = a4.w;
    }
    __syncthreads();

    // pgen = sigmoid(wh_p.ctx + ws_p.[h,c] + wx_p.x + bx_p)
    float scv = (tid < HH) ? hn[b * HH + tid] : cn[b * HH + (tid - HH)];
    float p = whp[tid] * sctx[tid] + wsp[tid] * scv
            + ((tid < HH) ? wxp[tid] * x[b * HH + tid] : 0.0f);
    red[tid] = p;
    __syncthreads();
#pragma unroll
    for (int o = 256; o > 0; o >>= 1) {
        if (tid < o) red[tid] += red[tid + o];
        __syncthreads();
    }
    if (tid == 0)
        dout[OFF_PG + (size_t)b * TT + t] = 1.0f / (1.0f + expf(-(red[0] + bxp[0])));
}

// ---------------- row softmax over V (in place in d_out), grid 2048 ----------------
__global__ __launch_bounds__(256) void k_vsoftmax(float* __restrict__ out)
{
    const int r = blockIdx.x, tid = threadIdx.x;
    float* row = out + (size_t)r * VV;
    float m = -INFINITY, s = 0.0f;
    for (int v = tid; v < VV; v += 256) {
        float l = row[v];
        if (l > m) { s = s * expf(m - l) + 1.0f; m = l; }
        else       { s += expf(l - m); }
    }
    __shared__ float sm[256], ss[256];
    sm[tid] = m; ss[tid] = s;
    __syncthreads();
#pragma unroll
    for (int o = 128; o > 0; o >>= 1) {
        if (tid < o) {
            float m2 = fmaxf(sm[tid], sm[tid + o]);
            ss[tid] = ss[tid] * expf(sm[tid] - m2) + ss[tid + o] * expf(sm[tid + o] - m2);
            sm[tid] = m2;
        }
        __syncthreads();
    }
    float M = sm[0], inv = 1.0f / ss[0];
    for (int v = tid; v < VV; v += 256)
        row[v] = expf(row[v] - M) * inv;
}

// ---------------- final h,c copy ----------------
__global__ void k_final(const float* __restrict__ h, const float* __restrict__ c,
                        float* __restrict__ out)
{
    int i = blockIdx.x * 256 + threadIdx.x;
    if (i < BB * HH) {
        out[OFF_H + i] = h[i];
        out[OFF_C + i] = c[i];
    }
}

// ---------------- host ----------------
extern "C" void kernel_launch(void* const* d_in, const int* in_sizes, int n_in,
                              void* d_out, int out_size)
{
    const int*   ids  = (const int*)d_in[0];
    const float* h0   = (const float*)d_in[1];
    const float* c0   = (const float*)d_in[2];
    const float* enc  = (const float*)d_in[3];
    const unsigned char* mask = (const unsigned char*)d_in[4];
    const float* emb  = (const float*)d_in[5];
    const float* Wr   = (const float*)d_in[6];
    const float* br   = (const float*)d_in[7];
    const float* Wih  = (const float*)d_in[8];
    const float* Whh  = (const float*)d_in[9];
    const float* bih  = (const float*)d_in[10];
    const float* bhh  = (const float*)d_in[11];
    const float* Wh_a = (const float*)d_in[12];
    const float* Ws_a = (const float*)d_in[13];
    const float* bs_a = (const float*)d_in[14];
    const float* v_a  = (const float*)d_in[15];
    const float* wh_p = (const float*)d_in[16];
    const float* ws_p = (const float*)d_in[17];
    const float* wx_p = (const float*)d_in[18];
    const float* bx_p = (const float*)d_in[19];
    const float* Wvr  = (const float*)d_in[20];
    const float* bvr  = (const float*)d_in[21];
    const float* Wvo  = (const float*)d_in[22];
    const float* bvo  = (const float*)d_in[23];
    float* out = (float*)d_out;

    float *encf, *hbuf, *cbuf, *ctx, *xp, *decp, *scoresp, *vredp;
    cudaGetSymbolAddress((void**)&encf,    g_enc_feat);
    cudaGetSymbolAddress((void**)&hbuf,    g_hbuf);
    cudaGetSymbolAddress((void**)&cbuf,    g_cbuf);
    cudaGetSymbolAddress((void**)&ctx,     g_ctx);
    cudaGetSymbolAddress((void**)&xp,      g_x);
    cudaGetSymbolAddress((void**)&decp,    g_dec);
    cudaGetSymbolAddress((void**)&scoresp, g_scores);
    cudaGetSymbolAddress((void**)&vredp,   g_vred);
    float* hA = hbuf;            float* hB = hbuf + BB * HH;
    float* cA = cbuf;            float* cB = cbuf + BB * HH;

    k_init<<<64, 256>>>(h0, c0, hA, cA, ctx);

    // enc_feat[b,s,h] = enc[b,s,:] . Wh_a[h,:]   (loop-invariant, hoisted)
    sgemm_abt<<<dim3(2, 100), 256>>>(enc, Wh_a, nullptr, encf, BB * SS, HH, H2);

    for (int t = 0; t < TT; t++) {
        const float* hi = (t & 1) ? hB : hA;
        const float* ci = (t & 1) ? cB : cA;
        float* ho = (t & 1) ? hA : hB;
        float* co = (t & 1) ? cA : cB;

        k_x<<<32, 256>>>(ids, emb, ctx, Wr, br, xp, t);
        k_gates<<<32, 256>>>(xp, hi, ci, Wih, Whh, bih, bhh, ho, co);
        k_rowlin<<<32, 256>>>(ho, HH, co, HH, Ws_a, 512, bs_a, decp, HH);
        k_scores<<<dim3(50, 32), 256>>>(encf, decp, v_a, mask, scoresp);
        k_attn_ctx<<<32, 512>>>(scoresp, enc, ho, co, xp,
                                wh_p, ws_p, wx_p, bx_p, ctx, out, t);
        k_rowlin<<<32, 256>>>(ho, HH, ctx, H2, Wvr, 768, bvr,
                              vredp + t * HH, TT * HH);
    }

    // batched vocab projection for ALL (b,t): logits -> d_out vocab region
    sgemm_abt<<<dim3(391, 16), 256>>>(vredp, Wvo, bvo, out, BB * TT, VV, HH);
    k_vsoftmax<<<BB * TT, 256>>>(out);

    // t=63 wrote buffer A
    k_final<<<32, 256>>>(hA, cA, out);
}